// round 5
// baseline (speedup 1.0000x reference)
#include <cuda_runtime.h>
#include <cstdint>

// Bulk-async (UBLKCP) pipeline reduction, v2.
// 148 persistent CTAs (1/SM), 1024 threads.
//   - Producer = warp 31 lane 0 (highest arbiter priority), issues
//     cp.async.bulk (3 streams x 32KB) into a 2-stage SMEM ring (192KB).
//   - Consumers = warps 0..30 (992 threads); warp-elected empty arrives
//     (31 arrives/tile instead of 992).
// Deterministic last-block finalize into d_out[0].

static constexpr int CTAS        = 148;
static constexpr int THREADS     = 1024;
static constexpr int STAGES      = 2;
static constexpr int TILE_FLOATS = 8192;
static constexpr int TILE_BYTES  = TILE_FLOATS * 4;            // 32 KB
static constexpr int TILE_F4     = TILE_FLOATS / 4;            // 2048
static constexpr int NCONS_WARPS = 31;
static constexpr int NCONS       = NCONS_WARPS * 32;           // 992
static constexpr int BAR_OFF     = STAGES * 3 * TILE_BYTES;    // 196608
static constexpr int SMEM_SIZE   = BAR_OFF + STAGES * 16;

__device__ float        g_partials[CTAS];
__device__ unsigned int g_done_count;     // zero-init; reset each call

__device__ __forceinline__ uint32_t smem_u32(const void* p) {
    uint32_t a;
    asm("{ .reg .u64 t; cvta.to.shared.u64 t, %1; cvt.u32.u64 %0, t; }" : "=r"(a) : "l"(p));
    return a;
}
__device__ __forceinline__ void mbar_init(uint32_t m, uint32_t cnt) {
    asm volatile("mbarrier.init.shared.b64 [%0], %1;" :: "r"(m), "r"(cnt) : "memory");
}
__device__ __forceinline__ void mbar_expect_tx(uint32_t m, uint32_t bytes) {
    asm volatile("mbarrier.arrive.expect_tx.shared.b64 _, [%0], %1;" :: "r"(m), "r"(bytes) : "memory");
}
__device__ __forceinline__ void mbar_arrive(uint32_t m) {
    asm volatile("mbarrier.arrive.shared.b64 _, [%0];" :: "r"(m) : "memory");
}
__device__ __forceinline__ void mbar_wait(uint32_t m, uint32_t parity) {
    asm volatile(
        "{\n\t"
        ".reg .pred P;\n\t"
        "LAB_%=:\n\t"
        "mbarrier.try_wait.parity.acquire.cta.shared::cta.b64 P, [%0], %1, 0x989680;\n\t"
        "@!P bra LAB_%=;\n\t"
        "}"
        :: "r"(m), "r"(parity) : "memory");
}
__device__ __forceinline__ void bulk_g2s(uint32_t dst, const void* src, uint32_t bytes, uint32_t mbar) {
    asm volatile(
        "cp.async.bulk.shared::cluster.global.mbarrier::complete_tx::bytes [%0], [%1], %2, [%3];"
        :: "r"(dst), "l"(src), "r"(bytes), "r"(mbar) : "memory");
}

__global__ __launch_bounds__(THREADS, 1) void trajloss_pipe2_kernel(
    const float* __restrict__ pred,   // N+1
    const float* __restrict__ xs,     // N
    const float* __restrict__ ys,     // N
    float* __restrict__ out,
    int n)
{
    extern __shared__ __align__(128) char smem[];
    const uint32_t sbase = smem_u32(smem);
    const int tid  = threadIdx.x;
    const int lane = tid & 31;
    const int wid  = tid >> 5;

    const int nTiles = n / TILE_FLOATS;

    if (tid == 0) {
        #pragma unroll
        for (int s = 0; s < STAGES; s++) {
            mbar_init(sbase + BAR_OFF + s * 16,     1);            // full: tx-based
            mbar_init(sbase + BAR_OFF + s * 16 + 8, NCONS_WARPS);  // empty: 1 arrive/warp
        }
    }
    __syncthreads();

    float acc0 = 0.0f, acc1 = 0.0f;

    if (wid == NCONS_WARPS) {
        // ---------------- producer warp (highest wid -> arbiter priority) ----
        if (lane == 0) {
            int k = 0;
            for (int t = blockIdx.x; t < nTiles; t += CTAS, k++) {
                int s = k & (STAGES - 1);
                uint32_t ph = 1u ^ (uint32_t)((k / STAGES) & 1);   // first pass free
                uint32_t full_b  = sbase + BAR_OFF + s * 16;
                uint32_t empty_b = full_b + 8;
                mbar_wait(empty_b, ph);
                mbar_expect_tx(full_b, 3 * TILE_BYTES);
                uint32_t stg = sbase + s * 3 * TILE_BYTES;
                long off = (long)t * TILE_FLOATS;
                bulk_g2s(stg,                  pred + off, TILE_BYTES, full_b);
                bulk_g2s(stg + TILE_BYTES,     xs   + off, TILE_BYTES, full_b);
                bulk_g2s(stg + 2 * TILE_BYTES, ys   + off, TILE_BYTES, full_b);
            }
        }
    } else {
        // ---------------- consumer warps 0..30 ----------------
        const int ct = tid;                 // 0..991
        int k = 0;
        for (int t = blockIdx.x; t < nTiles; t += CTAS, k++) {
            int s = k & (STAGES - 1);
            uint32_t ph = (uint32_t)((k / STAGES) & 1);
            uint32_t full_b  = sbase + BAR_OFF + s * 16;
            uint32_t empty_b = full_b + 8;
            mbar_wait(full_b, ph);

            const char* stg = smem + s * 3 * TILE_BYTES;
            const float4* p4 = reinterpret_cast<const float4*>(stg);
            const float*  pf = reinterpret_cast<const float*>(stg);
            const float4* x4 = reinterpret_cast<const float4*>(stg + TILE_BYTES);
            const float4* y4 = reinterpret_cast<const float4*>(stg + 2 * TILE_BYTES);

            for (int j = ct; j < TILE_F4; j += NCONS) {
                float4 p  = p4[j];
                float4 xv = x4[j];
                float4 yv = y4[j];
                float  pn = (j + 1 < TILE_F4)
                              ? pf[4 * j + 4]
                              : __ldg(&pred[(long)t * TILE_FLOATS + TILE_FLOATS]);

                float dx0 = xv.x - p.x, dx1 = xv.y - p.y;
                float dx2 = xv.z - p.z, dx3 = xv.w - p.w;
                float dy0 = yv.x - p.y, dy1 = yv.y - p.z;
                float dy2 = yv.z - p.w, dy3 = yv.w - pn;

                acc0 = fmaf(dx0, dx0, acc0); acc1 = fmaf(dy0, dy0, acc1);
                acc0 = fmaf(dx1, dx1, acc0); acc1 = fmaf(dy1, dy1, acc1);
                acc0 = fmaf(dx2, dx2, acc0); acc1 = fmaf(dy2, dy2, acc1);
                acc0 = fmaf(dx3, dx3, acc0); acc1 = fmaf(dy3, dy3, acc1);
            }
            __syncwarp();
            if (lane == 0) mbar_arrive(empty_b);   // 1 arrive per warp
        }
    }

    // ---------------- remainder (n % TILE_FLOATS == 0 for N=2^24) ----------
    {
        int base = nTiles * TILE_FLOATS;
        for (int i = base + blockIdx.x * THREADS + tid; i < n; i += CTAS * THREADS) {
            float dx = xs[i] - pred[i];
            float dy = ys[i] - pred[i + 1];
            acc0 = fmaf(dx, dx, acc0);
            acc1 = fmaf(dy, dy, acc1);
        }
    }

    float acc = acc0 + acc1;

    // ---------------- intra-block reduction (32 warps) ----------------
    #pragma unroll
    for (int off = 16; off > 0; off >>= 1)
        acc += __shfl_xor_sync(0xFFFFFFFFu, acc, off);

    __shared__ float warp_sums[32];
    __shared__ bool  is_last;
    __syncthreads();                 // pipeline fully drained before smem reuse
    if (lane == 0) warp_sums[wid] = acc;
    __syncthreads();

    if (wid == 0) {
        float v = warp_sums[lane];
        #pragma unroll
        for (int off = 16; off > 0; off >>= 1)
            v += __shfl_xor_sync(0xFFFFFFFFu, v, off);
        if (lane == 0) {
            g_partials[blockIdx.x] = v;
            __threadfence();
            unsigned int prev = atomicAdd(&g_done_count, 1u);
            is_last = (prev == (unsigned int)(CTAS - 1));
        }
    }
    __syncthreads();

    // ---------------- last block finalizes ----------------
    if (is_last) {
        float t = (tid < CTAS) ? g_partials[tid] : 0.0f;

        #pragma unroll
        for (int off = 16; off > 0; off >>= 1)
            t += __shfl_xor_sync(0xFFFFFFFFu, t, off);

        if (lane == 0) warp_sums[wid] = t;
        __syncthreads();

        if (wid == 0) {
            float v = warp_sums[lane];
            #pragma unroll
            for (int off = 16; off > 0; off >>= 1)
                v += __shfl_xor_sync(0xFFFFFFFFu, v, off);
            if (lane == 0) {
                out[0] = v;
                g_done_count = 0;    // graph-replay safe reset
            }
        }
    }
}

extern "C" void kernel_launch(void* const* d_in, const int* in_sizes, int n_in,
                              void* d_out, int out_size)
{
    const float* pred = (const float*)d_in[0];   // N+1
    const float* xs   = (const float*)d_in[1];   // N
    const float* ys   = (const float*)d_in[2];   // N
    float* out        = (float*)d_out;

    int n = in_sizes[1];

    cudaFuncSetAttribute(trajloss_pipe2_kernel,
                         cudaFuncAttributeMaxDynamicSharedMemorySize, SMEM_SIZE);
    trajloss_pipe2_kernel<<<CTAS, THREADS, SMEM_SIZE>>>(pred, xs, ys, out, n);
}

// round 6
// speedup vs baseline: 1.0226x; 1.0226x over previous
#include <cuda_runtime.h>
#include <cstdint>

// Dual-engine reduction: TMA bulk-async pipeline (60% of data) + direct
// per-warp LDG streaming (40% of data) running concurrently per SM, so the
// two demand paths' in-flight bytes add toward the DRAM ceiling.
// 148 persistent CTAs (1/SM), 1024 threads:
//   warp 31 lane 0 = producer (cp.async.bulk, 4-stage ring, 48KB+16B/stage)
//   warps 0..30    = consumers (direct LDG burst, then staged-tile reduce)
// Deterministic last-block finalize into d_out[0].

static constexpr int CTAS        = 148;
static constexpr int THREADS     = 1024;
static constexpr int STAGES      = 4;
static constexpr int TILE_FLOATS = 4096;
static constexpr int TILE_BYTES  = TILE_FLOATS * 4;          // 16384
static constexpr int TILE_F4     = TILE_FLOATS / 4;          // 1024
static constexpr int NCONS_WARPS = 31;
static constexpr int NCONS       = NCONS_WARPS * 32;         // 992
static constexpr int PRED_BYTES  = TILE_BYTES + 16;          // +4 floats for shift
static constexpr int STAGE_BYTES = PRED_BYTES + 2 * TILE_BYTES;   // 49168
static constexpr int X_OFF       = PRED_BYTES;                    // 16400
static constexpr int Y_OFF       = PRED_BYTES + TILE_BYTES;       // 32784
static constexpr int BAR_OFF     = STAGES * STAGE_BYTES;          // 196672
static constexpr int SMEM_SIZE   = BAR_OFF + STAGES * 16;
static constexpr long GS         = (long)CTAS * NCONS;            // 146816

__device__ float        g_partials[CTAS];
__device__ unsigned int g_done_count;     // zero-init; reset each call

__device__ __forceinline__ uint32_t smem_u32(const void* p) {
    uint32_t a;
    asm("{ .reg .u64 t; cvta.to.shared.u64 t, %1; cvt.u32.u64 %0, t; }" : "=r"(a) : "l"(p));
    return a;
}
__device__ __forceinline__ void mbar_init(uint32_t m, uint32_t cnt) {
    asm volatile("mbarrier.init.shared.b64 [%0], %1;" :: "r"(m), "r"(cnt) : "memory");
}
__device__ __forceinline__ void mbar_expect_tx(uint32_t m, uint32_t bytes) {
    asm volatile("mbarrier.arrive.expect_tx.shared.b64 _, [%0], %1;" :: "r"(m), "r"(bytes) : "memory");
}
__device__ __forceinline__ void mbar_arrive(uint32_t m) {
    asm volatile("mbarrier.arrive.shared.b64 _, [%0];" :: "r"(m) : "memory");
}
__device__ __forceinline__ void mbar_wait(uint32_t m, uint32_t parity) {
    asm volatile(
        "{\n\t"
        ".reg .pred P;\n\t"
        "LAB_%=:\n\t"
        "mbarrier.try_wait.parity.acquire.cta.shared::cta.b64 P, [%0], %1, 0x989680;\n\t"
        "@!P bra LAB_%=;\n\t"
        "}"
        :: "r"(m), "r"(parity) : "memory");
}
__device__ __forceinline__ void bulk_g2s(uint32_t dst, const void* src, uint32_t bytes, uint32_t mbar) {
    asm volatile(
        "cp.async.bulk.shared::cluster.global.mbarrier::complete_tx::bytes [%0], [%1], %2, [%3];"
        :: "r"(dst), "l"(src), "r"(bytes), "r"(mbar) : "memory");
}

__global__ __launch_bounds__(THREADS, 1) void trajloss_dual_kernel(
    const float* __restrict__ pred,   // N+1
    const float* __restrict__ xs,     // N
    const float* __restrict__ ys,     // N
    float* __restrict__ out,
    int n,
    int nTiles)                       // pipeline region = nTiles * TILE_FLOATS
{
    extern __shared__ __align__(128) char smem[];
    const uint32_t sbase = smem_u32(smem);
    const int tid  = threadIdx.x;
    const int lane = tid & 31;
    const int wid  = tid >> 5;

    const long P      = (long)nTiles * TILE_FLOATS;   // pipeline region floats
    const long P4     = P >> 2;
    const long D4     = ((long)n - P) >> 2;           // direct region float4s
    const int  Md     = (int)((D4 + GS - 1) / GS);    // direct iters per consumer

    const float4* __restrict__ pred4g = reinterpret_cast<const float4*>(pred);
    const float4* __restrict__ x4g    = reinterpret_cast<const float4*>(xs);
    const float4* __restrict__ y4g    = reinterpret_cast<const float4*>(ys);

    if (tid == 0) {
        #pragma unroll
        for (int s = 0; s < STAGES; s++) {
            mbar_init(sbase + BAR_OFF + s * 16,     1);            // full: tx-based
            mbar_init(sbase + BAR_OFF + s * 16 + 8, NCONS_WARPS);  // empty: 1/warp
        }
    }
    __syncthreads();

    float acc0 = 0.0f, acc1 = 0.0f;

    if (wid == NCONS_WARPS) {
        // ---------------- producer warp (highest wid) ----------------
        if (lane == 0) {
            int k = 0;
            for (int t = blockIdx.x; t < nTiles; t += CTAS, k++) {
                int s = k & (STAGES - 1);
                uint32_t ph = 1u ^ (uint32_t)((k / STAGES) & 1);
                uint32_t full_b  = sbase + BAR_OFF + s * 16;
                uint32_t empty_b = full_b + 8;
                mbar_wait(empty_b, ph);
                mbar_expect_tx(full_b, STAGE_BYTES);
                uint32_t stg = sbase + s * STAGE_BYTES;
                long off = (long)t * TILE_FLOATS;
                bulk_g2s(stg,         pred + off, PRED_BYTES, full_b);  // +16B shift
                bulk_g2s(stg + X_OFF, xs   + off, TILE_BYTES, full_b);
                bulk_g2s(stg + Y_OFF, ys   + off, TILE_BYTES, full_b);
            }
        }
    } else {
        // ---------------- consumer warps 0..30 ----------------
        const int  ct  = tid;                          // 0..991
        const long cid = (long)blockIdx.x * NCONS + ct;
        int m = 0;                                     // direct-region cursor
        int k = 0;
        for (int t = blockIdx.x; t < nTiles; t += CTAS, k++) {
            // -- direct-engine burst (LDG demand while TMA fills the stage) --
            if (m < Md) {
                long idx4 = (long)m * GS + cid;
                if (idx4 < D4) {
                    long g4 = P4 + idx4;
                    float4 p  = pred4g[g4];
                    float4 xv = __ldcs(&x4g[g4]);
                    float4 yv = __ldcs(&y4g[g4]);
                    float  pn = pred[g4 * 4 + 4];
                    float dx0 = xv.x - p.x, dx1 = xv.y - p.y;
                    float dx2 = xv.z - p.z, dx3 = xv.w - p.w;
                    float dy0 = yv.x - p.y, dy1 = yv.y - p.z;
                    float dy2 = yv.z - p.w, dy3 = yv.w - pn;
                    acc0 = fmaf(dx0, dx0, acc0); acc1 = fmaf(dy0, dy0, acc1);
                    acc0 = fmaf(dx1, dx1, acc0); acc1 = fmaf(dy1, dy1, acc1);
                    acc0 = fmaf(dx2, dx2, acc0); acc1 = fmaf(dy2, dy2, acc1);
                    acc0 = fmaf(dx3, dx3, acc0); acc1 = fmaf(dy3, dy3, acc1);
                }
                m++;
            }

            // -- pipeline engine: consume staged tile --
            int s = k & (STAGES - 1);
            uint32_t ph = (uint32_t)((k / STAGES) & 1);
            uint32_t full_b  = sbase + BAR_OFF + s * 16;
            uint32_t empty_b = full_b + 8;
            mbar_wait(full_b, ph);

            const char* stg = smem + s * STAGE_BYTES;
            const float4* p4 = reinterpret_cast<const float4*>(stg);
            const float*  pf = reinterpret_cast<const float*>(stg);
            const float4* x4 = reinterpret_cast<const float4*>(stg + X_OFF);
            const float4* y4 = reinterpret_cast<const float4*>(stg + Y_OFF);

            #pragma unroll 2
            for (int j = ct; j < TILE_F4; j += NCONS) {
                float4 p  = p4[j];
                float4 xv = x4[j];
                float4 yv = y4[j];
                float  pn = pf[4 * j + 4];             // always valid (+16B copy)

                float dx0 = xv.x - p.x, dx1 = xv.y - p.y;
                float dx2 = xv.z - p.z, dx3 = xv.w - p.w;
                float dy0 = yv.x - p.y, dy1 = yv.y - p.z;
                float dy2 = yv.z - p.w, dy3 = yv.w - pn;

                acc0 = fmaf(dx0, dx0, acc0); acc1 = fmaf(dy0, dy0, acc1);
                acc0 = fmaf(dx1, dx1, acc0); acc1 = fmaf(dy1, dy1, acc1);
                acc0 = fmaf(dx2, dx2, acc0); acc1 = fmaf(dy2, dy2, acc1);
                acc0 = fmaf(dx3, dx3, acc0); acc1 = fmaf(dy3, dy3, acc1);
            }
            __syncwarp();
            if (lane == 0) mbar_arrive(empty_b);
        }

        // -- leftover direct iterations (CTAs with fewer tiles than Md) --
        for (; m < Md; m++) {
            long idx4 = (long)m * GS + cid;
            if (idx4 < D4) {
                long g4 = P4 + idx4;
                float4 p  = pred4g[g4];
                float4 xv = __ldcs(&x4g[g4]);
                float4 yv = __ldcs(&y4g[g4]);
                float  pn = pred[g4 * 4 + 4];
                float dx0 = xv.x - p.x, dx1 = xv.y - p.y;
                float dx2 = xv.z - p.z, dx3 = xv.w - p.w;
                float dy0 = yv.x - p.y, dy1 = yv.y - p.z;
                float dy2 = yv.z - p.w, dy3 = yv.w - pn;
                acc0 = fmaf(dx0, dx0, acc0); acc1 = fmaf(dy0, dy0, acc1);
                acc0 = fmaf(dx1, dx1, acc0); acc1 = fmaf(dy1, dy1, acc1);
                acc0 = fmaf(dx2, dx2, acc0); acc1 = fmaf(dy2, dy2, acc1);
                acc0 = fmaf(dx3, dx3, acc0); acc1 = fmaf(dy3, dy3, acc1);
            }
        }
    }

    float acc = acc0 + acc1;

    // ---------------- intra-block reduction ----------------
    #pragma unroll
    for (int off = 16; off > 0; off >>= 1)
        acc += __shfl_xor_sync(0xFFFFFFFFu, acc, off);

    __shared__ float warp_sums[32];
    __shared__ bool  is_last;
    __syncthreads();                 // pipeline drained before smem reuse
    if (lane == 0) warp_sums[wid] = acc;
    __syncthreads();

    if (wid == 0) {
        float v = warp_sums[lane];
        #pragma unroll
        for (int off = 16; off > 0; off >>= 1)
            v += __shfl_xor_sync(0xFFFFFFFFu, v, off);
        if (lane == 0) {
            g_partials[blockIdx.x] = v;
            __threadfence();
            unsigned int prev = atomicAdd(&g_done_count, 1u);
            is_last = (prev == (unsigned int)(CTAS - 1));
        }
    }
    __syncthreads();

    // ---------------- last block finalizes ----------------
    if (is_last) {
        float t = (tid < CTAS) ? g_partials[tid] : 0.0f;

        #pragma unroll
        for (int off = 16; off > 0; off >>= 1)
            t += __shfl_xor_sync(0xFFFFFFFFu, t, off);

        if (lane == 0) warp_sums[wid] = t;
        __syncthreads();

        if (wid == 0) {
            float v = warp_sums[lane];
            #pragma unroll
            for (int off = 16; off > 0; off >>= 1)
                v += __shfl_xor_sync(0xFFFFFFFFu, v, off);
            if (lane == 0) {
                out[0] = v;
                g_done_count = 0;    // graph-replay safe reset
            }
        }
    }
}

extern "C" void kernel_launch(void* const* d_in, const int* in_sizes, int n_in,
                              void* d_out, int out_size)
{
    const float* pred = (const float*)d_in[0];   // N+1
    const float* xs   = (const float*)d_in[1];   // N
    const float* ys   = (const float*)d_in[2];   // N
    float* out        = (float*)d_out;

    int n = in_sizes[1];

    // ~60% of data through the TMA pipeline, ~40% through direct LDG.
    int nTiles = (int)(((long)n * 3 / 5) / TILE_FLOATS);

    cudaFuncSetAttribute(trajloss_dual_kernel,
                         cudaFuncAttributeMaxDynamicSharedMemorySize, SMEM_SIZE);
    trajloss_dual_kernel<<<CTAS, THREADS, SMEM_SIZE>>>(pred, xs, ys, out, n, nTiles);
}